// round 3
// baseline (speedup 1.0000x reference)
#include <cuda_runtime.h>
#include <math.h>
#include <stdint.h>

#define B_TOK 16384
#define D_DIM 2048
#define E_NUM 64
#define R_DIM 128
#define NASSIGN (2 * B_TOK)
#define CAP 640

// ---------------- scratch (static __device__ globals; no allocations) ----------------
__device__ float g_enc[(size_t)B_TOK * D_DIM];          // 134 MB
__device__ float g_logits[(size_t)B_TOK * E_NUM];       // 4 MB
__device__ int   g_eid[NASSIGN];
__device__ float g_w[NASSIGN];                          // weight if valid else 0
__device__ int   g_rows[E_NUM * CAP];                   // assignment ids per expert
__device__ int   g_cnt[E_NUM];
__device__ float g_h[(size_t)E_NUM * CAP * R_DIM];      // 21 MB
__device__ float g_dbuf[(size_t)NASSIGN * D_DIM];       // 268 MB

// =====================================================================
// helpers
// =====================================================================
__device__ __forceinline__ uint32_t smem_u32(const void* p) {
    uint32_t a;
    asm("{ .reg .u64 t; cvta.to.shared.u64 t, %1; cvt.u32.u64 %0, t; }" : "=r"(a) : "l"(p));
    return a;
}
// split fp32 -> (tf32 hi, tf32 lo) with lo = tf32(x - hi)
__device__ __forceinline__ void tf32_split(float x, uint32_t& h, uint32_t& l) {
    uint32_t hu;
    asm("cvt.rna.tf32.f32 %0, %1;" : "=r"(hu) : "f"(x));
    float lf = x - __uint_as_float(hu);
    uint32_t lu;
    asm("cvt.rna.tf32.f32 %0, %1;" : "=r"(lu) : "f"(lf));
    h = hu; l = lu;
}
__device__ __forceinline__ void sts_v4u(uint32_t addr, uint32_t a, uint32_t b, uint32_t c, uint32_t d) {
    asm volatile("st.shared.v4.b32 [%0], {%1,%2,%3,%4};"
                 :: "r"(addr), "r"(a), "r"(b), "r"(c), "r"(d) : "memory");
}
__device__ __forceinline__ void lds_v2(uint32_t addr, uint32_t& a, uint32_t& b) {
    asm volatile("ld.shared.v2.b32 {%0,%1}, [%2];" : "=r"(a), "=r"(b) : "r"(addr));
}
__device__ __forceinline__ void mma_tf32_16n8k8(float* c, const uint32_t* a, uint32_t b0, uint32_t b1) {
    asm volatile(
        "mma.sync.aligned.m16n8k8.row.col.f32.tf32.tf32.f32 "
        "{%0,%1,%2,%3}, {%4,%5,%6,%7}, {%8,%9}, {%0,%1,%2,%3};"
        : "+f"(c[0]), "+f"(c[1]), "+f"(c[2]), "+f"(c[3])
        : "r"(a[0]), "r"(a[1]), "r"(a[2]), "r"(a[3]), "r"(b0), "r"(b1));
}

// =====================================================================
// Stage 1: enc = x @ We^T + be via mma.sync tf32 (3x split)
// BM=128 BN=128 BK=32, 256 thr (8 warps, 4x2), warp tile 32x64
// SMEM: per stage, A and B tiles of 128 x 36 float2 (hi,lo interleaved)
// =====================================================================
#define EB_M 128
#define EB_N 128
#define EB_K 32
#define KST 36                          // float2 per smem row (padded)
#define TILE_BYTES (128 * KST * 8)      // 36864
#define STAGE_BYTES (2 * TILE_BYTES)    // A + B = 73728
#define ENC_SMEM (2 * STAGE_BYTES)      // 147456

__global__ void __launch_bounds__(256, 1) k_enc_mma(const float* __restrict__ A,
                                                    const float* __restrict__ W,
                                                    const float* __restrict__ bias) {
    extern __shared__ char smraw[];
    const uint32_t sb = smem_u32(smraw);
    const int tid = threadIdx.x;
    const int lane = tid & 31;
    const int wid = tid >> 5;
    const int wm = wid & 3;             // 0..3 -> m offset 32 each
    const int wn = wid >> 2;            // 0..1 -> n offset 64 each
    const int g = lane >> 2;            // 0..7
    const int t = lane & 3;             // 0..3
    const int m0 = blockIdx.y * EB_M;
    const int n0 = blockIdx.x * EB_N;

    // ---- global loader mapping: 256 threads cover 128 rows x 32 cols for A and B
    const int lrow = tid >> 1;          // 0..127
    const int lk = (tid & 1) * 16;      // 0 or 16
    const float* aG = A + (size_t)(m0 + lrow) * D_DIM + lk;
    const float* bG = W + (size_t)(n0 + lrow) * D_DIM + lk;
    const uint32_t strowA = (uint32_t)(lrow * KST + lk) * 8u;                 // byte offset in A tile
    const uint32_t strowB = (uint32_t)(lrow * KST + lk) * 8u + TILE_BYTES;    // in B tile

    float4 ra[4], rb[4];

    float acc[2][8][4];
#pragma unroll
    for (int i = 0; i < 2; i++)
#pragma unroll
        for (int j = 0; j < 8; j++)
#pragma unroll
            for (int q = 0; q < 4; q++) acc[i][j][q] = 0.0f;

    // fragment base addresses (byte), excluding stage offset
    const uint32_t aFrag = (uint32_t)((wm * 32 + g) * KST + t) * 8u;
    const uint32_t bFrag = (uint32_t)((wn * 64 + g) * KST + t) * 8u + TILE_BYTES;

    const int NC = D_DIM / EB_K;        // 64

    // ---- prologue: load + store stage 0
#pragma unroll
    for (int j = 0; j < 4; j++) {
        ra[j] = *(const float4*)(aG + j * 4);
        rb[j] = *(const float4*)(bG + j * 4);
    }
    {
        const uint32_t base = sb;
#pragma unroll
        for (int j = 0; j < 4; j++) {
            uint32_t h0, l0, h1, l1, h2, l2, h3, l3;
            tf32_split(ra[j].x, h0, l0); tf32_split(ra[j].y, h1, l1);
            tf32_split(ra[j].z, h2, l2); tf32_split(ra[j].w, h3, l3);
            uint32_t ad = base + strowA + (uint32_t)j * 32u;
            sts_v4u(ad, h0, l0, h1, l1);
            sts_v4u(ad + 16u, h2, l2, h3, l3);
            tf32_split(rb[j].x, h0, l0); tf32_split(rb[j].y, h1, l1);
            tf32_split(rb[j].z, h2, l2); tf32_split(rb[j].w, h3, l3);
            uint32_t bd = base + strowB + (uint32_t)j * 32u;
            sts_v4u(bd, h0, l0, h1, l1);
            sts_v4u(bd + 16u, h2, l2, h3, l3);
        }
    }
    __syncthreads();

#pragma unroll 1
    for (int c = 0; c < NC; c++) {
        // prefetch next chunk
        if (c + 1 < NC) {
            const int koff = (c + 1) * EB_K;
#pragma unroll
            for (int j = 0; j < 4; j++) {
                ra[j] = *(const float4*)(aG + koff + j * 4);
                rb[j] = *(const float4*)(bG + koff + j * 4);
            }
        }
        // compute on stage c&1
        const uint32_t stage = sb + (uint32_t)(c & 1) * STAGE_BYTES;
        const uint32_t ab = stage + aFrag;
        const uint32_t bb = stage + bFrag;
#pragma unroll
        for (int k8 = 0; k8 < 4; k8++) {
            const uint32_t kc = (uint32_t)(k8 * 8) * 8u;  // byte offset along k (float2=8B)
            uint32_t ah[2][4], al[2][4];
#pragma unroll
            for (int mi = 0; mi < 2; mi++) {
                const uint32_t a0 = ab + (uint32_t)(mi * 16 * KST) * 8u + kc;
                lds_v2(a0,                      ah[mi][0], al[mi][0]);   // (g, t)
                lds_v2(a0 + (uint32_t)(8 * KST) * 8u, ah[mi][1], al[mi][1]); // (g+8, t)
                lds_v2(a0 + 32u,                ah[mi][2], al[mi][2]);   // (g, t+4)
                lds_v2(a0 + (uint32_t)(8 * KST) * 8u + 32u, ah[mi][3], al[mi][3]);
            }
#pragma unroll
            for (int ni = 0; ni < 8; ni++) {
                const uint32_t b0a = bb + (uint32_t)(ni * 8 * KST) * 8u + kc;
                uint32_t bh0, bl0, bh1, bl1;
                lds_v2(b0a, bh0, bl0);          // (k=t,   n=g)
                lds_v2(b0a + 32u, bh1, bl1);    // (k=t+4, n=g)
#pragma unroll
                for (int mi = 0; mi < 2; mi++) {
                    mma_tf32_16n8k8(acc[mi][ni], ah[mi], bh0, bh1);
                    mma_tf32_16n8k8(acc[mi][ni], ah[mi], bl0, bl1);
                    mma_tf32_16n8k8(acc[mi][ni], al[mi], bh0, bh1);
                }
            }
        }
        // store next stage
        if (c + 1 < NC) {
            const uint32_t base = sb + (uint32_t)((c + 1) & 1) * STAGE_BYTES;
#pragma unroll
            for (int j = 0; j < 4; j++) {
                uint32_t h0, l0, h1, l1, h2, l2, h3, l3;
                tf32_split(ra[j].x, h0, l0); tf32_split(ra[j].y, h1, l1);
                tf32_split(ra[j].z, h2, l2); tf32_split(ra[j].w, h3, l3);
                uint32_t ad = base + strowA + (uint32_t)j * 32u;
                sts_v4u(ad, h0, l0, h1, l1);
                sts_v4u(ad + 16u, h2, l2, h3, l3);
                tf32_split(rb[j].x, h0, l0); tf32_split(rb[j].y, h1, l1);
                tf32_split(rb[j].z, h2, l2); tf32_split(rb[j].w, h3, l3);
                uint32_t bd = base + strowB + (uint32_t)j * 32u;
                sts_v4u(bd, h0, l0, h1, l1);
                sts_v4u(bd + 16u, h2, l2, h3, l3);
            }
            __syncthreads();
        }
    }

    // ---- epilogue: add bias, store
#pragma unroll
    for (int mi = 0; mi < 2; mi++) {
        const int r0 = m0 + wm * 32 + mi * 16 + g;
        const int r1 = r0 + 8;
#pragma unroll
        for (int ni = 0; ni < 8; ni++) {
            const int col = n0 + wn * 64 + ni * 8 + 2 * t;
            const float2 bv = *(const float2*)(bias + col);
            float2 o0, o1;
            o0.x = acc[mi][ni][0] + bv.x; o0.y = acc[mi][ni][1] + bv.y;
            o1.x = acc[mi][ni][2] + bv.x; o1.y = acc[mi][ni][3] + bv.y;
            *(float2*)(g_enc + (size_t)r0 * D_DIM + col) = o0;
            *(float2*)(g_enc + (size_t)r1 * D_DIM + col) = o1;
        }
    }
}

// =====================================================================
// Stage 2: logits = enc @ Wg^T  (M=16384, N=64, K=2048, fp32 SIMT)
// =====================================================================
__global__ void __launch_bounds__(256) k_gemm_logits(const float* __restrict__ Wg) {
    __shared__ float As[8][128];
    __shared__ float Bs[8][64];
    const int tid = threadIdx.x;
    const int m0 = blockIdx.y * 128;
    const int ty = tid >> 4, tx = tid & 15;
    const int lr = tid >> 1;
    const int lk = (tid & 1) * 4;
    const float* aptr = g_enc + (size_t)(m0 + lr) * D_DIM + lk;
    const float* bptr = Wg + (size_t)(tid >> 1) * D_DIM + lk;

    float acc[8][4];
#pragma unroll
    for (int i = 0; i < 8; i++)
#pragma unroll
        for (int j = 0; j < 4; j++) acc[i][j] = 0.0f;

    for (int k0 = 0; k0 < D_DIM; k0 += 8) {
        float4 av = *(const float4*)(aptr + k0);
        float4 bv = make_float4(0.f, 0.f, 0.f, 0.f);
        if (tid < 128) bv = *(const float4*)(bptr + k0);
        __syncthreads();
        As[lk + 0][lr] = av.x; As[lk + 1][lr] = av.y;
        As[lk + 2][lr] = av.z; As[lk + 3][lr] = av.w;
        if (tid < 128) {
            Bs[lk + 0][lr] = bv.x; Bs[lk + 1][lr] = bv.y;
            Bs[lk + 2][lr] = bv.z; Bs[lk + 3][lr] = bv.w;
        }
        __syncthreads();
#pragma unroll
        for (int kk = 0; kk < 8; kk++) {
            float4 a0 = *(const float4*)&As[kk][ty * 8];
            float4 a1 = *(const float4*)&As[kk][ty * 8 + 4];
            float4 b0 = *(const float4*)&Bs[kk][tx * 4];
            float a[8] = {a0.x, a0.y, a0.z, a0.w, a1.x, a1.y, a1.z, a1.w};
            float b[4] = {b0.x, b0.y, b0.z, b0.w};
#pragma unroll
            for (int i = 0; i < 8; i++)
#pragma unroll
                for (int j = 0; j < 4; j++) acc[i][j] += a[i] * b[j];
        }
    }
#pragma unroll
    for (int i = 0; i < 8; i++)
#pragma unroll
        for (int j = 0; j < 4; j++)
            g_logits[(size_t)(m0 + ty * 8 + i) * E_NUM + tx * 4 + j] = acc[i][j];
}

// =====================================================================
// Stage 3: per-token top-2 + masked softmax
// =====================================================================
__global__ void __launch_bounds__(256) k_route() {
    const int t = blockIdx.x * blockDim.x + threadIdx.x;
    if (t >= B_TOK) return;
    const float* lg = g_logits + (size_t)t * E_NUM;
    float v0 = -INFINITY; int i0 = 0;
#pragma unroll 8
    for (int e = 0; e < E_NUM; e++) {
        float v = lg[e];
        if (v > v0) { v0 = v; i0 = e; }
    }
    float v1 = -INFINITY; int i1 = 0;
#pragma unroll 8
    for (int e = 0; e < E_NUM; e++) {
        if (e == i0) continue;
        float v = lg[e];
        if (v > v1) { v1 = v; i1 = e; }
    }
    float e1 = expf(v1 - v0);
    float s = 1.0f + e1 + 1e-12f;
    float w0 = 1.0f / s;
    float w1 = e1 / s;
    g_eid[2 * t]     = i0;
    g_eid[2 * t + 1] = i1;
    g_w[2 * t]       = (w0 > 1e-12f) ? w0 : 0.0f;
    g_w[2 * t + 1]   = (w1 > 1e-12f) ? w1 : 0.0f;
}

// =====================================================================
// Stage 4: deterministic capacity scan
// =====================================================================
__global__ void __launch_bounds__(256) k_capacity() {
    const int e = blockIdx.x;
    const int tid = threadIdx.x;
    const int lane = tid & 31;
    const int wrp = tid >> 5;
    __shared__ int warp_cnt[8];
    int base = 0;
    for (int n0 = 0; n0 < NASSIGN; n0 += 256) {
        const int n = n0 + tid;
        const bool flag = (g_eid[n] == e) && (g_w[n] > 0.0f);
        unsigned m = __ballot_sync(0xffffffffu, flag);
        if (lane == 0) warp_cnt[wrp] = __popc(m);
        __syncthreads();
        int off = 0, tot = 0;
#pragma unroll
        for (int i = 0; i < 8; i++) {
            int c = warp_cnt[i];
            if (i < wrp) off += c;
            tot += c;
        }
        if (flag) {
            int pos = base + off + __popc(m & ((1u << lane) - 1u));
            if (pos < CAP) g_rows[e * CAP + pos] = n;
            else           g_w[n] = 0.0f;
        }
        base += tot;
        __syncthreads();
    }
    if (tid == 0) g_cnt[e] = (base < CAP) ? base : CAP;
}

// =====================================================================
// Stage 5: H = silu(X_gathered @ U_e^T)
// =====================================================================
__device__ __forceinline__ float silu_f(float v) {
    return v / (1.0f + expf(-v));
}

__global__ void __launch_bounds__(256) k_gemm_expert1(const float* __restrict__ U) {
    const int e = blockIdx.y;
    const int cnt = g_cnt[e];
    const int m0 = blockIdx.x * 64;
    if (m0 >= cnt) return;
    __shared__ float As[8][64];
    __shared__ float Bs[8][128];
    const int tid = threadIdx.x;
    const int ty = tid >> 4, tx = tid & 15;
    const int lr = tid >> 1;
    const int lk = (tid & 1) * 4;

    int atok = -1;
    if (tid < 128) {
        if (m0 + lr < cnt) atok = g_rows[e * CAP + m0 + lr] >> 1;
    }
    const float* aptr = (atok >= 0) ? (g_enc + (size_t)atok * D_DIM + lk) : g_enc;
    const float* bptr = U + ((size_t)e * R_DIM + lr) * D_DIM + lk;

    float acc[4][8];
#pragma unroll
    for (int i = 0; i < 4; i++)
#pragma unroll
        for (int j = 0; j < 8; j++) acc[i][j] = 0.0f;

    for (int k0 = 0; k0 < D_DIM; k0 += 8) {
        float4 av = make_float4(0.f, 0.f, 0.f, 0.f);
        if (atok >= 0) av = *(const float4*)(aptr + k0);
        float4 bv = *(const float4*)(bptr + k0);
        __syncthreads();
        if (tid < 128) {
            As[lk + 0][lr] = av.x; As[lk + 1][lr] = av.y;
            As[lk + 2][lr] = av.z; As[lk + 3][lr] = av.w;
        }
        Bs[lk + 0][lr] = bv.x; Bs[lk + 1][lr] = bv.y;
        Bs[lk + 2][lr] = bv.z; Bs[lk + 3][lr] = bv.w;
        __syncthreads();
#pragma unroll
        for (int kk = 0; kk < 8; kk++) {
            float4 a0 = *(const float4*)&As[kk][ty * 4];
            float4 b0 = *(const float4*)&Bs[kk][tx * 8];
            float4 b1 = *(const float4*)&Bs[kk][tx * 8 + 4];
            float a[4] = {a0.x, a0.y, a0.z, a0.w};
            float b[8] = {b0.x, b0.y, b0.z, b0.w, b1.x, b1.y, b1.z, b1.w};
#pragma unroll
            for (int i = 0; i < 4; i++)
#pragma unroll
                for (int j = 0; j < 8; j++) acc[i][j] += a[i] * b[j];
        }
    }
#pragma unroll
    for (int i = 0; i < 4; i++) {
        int m = m0 + ty * 4 + i;
        if (m < cnt) {
            float* hp = g_h + ((size_t)e * CAP + m) * R_DIM + tx * 8;
#pragma unroll
            for (int j = 0; j < 8; j++) hp[j] = silu_f(acc[i][j]);
        }
    }
}

// =====================================================================
// Stage 6: dbuf[n] = (w * gamma_e) * (H @ V_e^T)
// =====================================================================
__global__ void __launch_bounds__(256) k_gemm_expert2(const float* __restrict__ V,
                                                      const float* __restrict__ gamma) {
    const int e = blockIdx.z;
    const int cnt = g_cnt[e];
    const int m0 = blockIdx.y * 64;
    if (m0 >= cnt) return;
    const int n0 = blockIdx.x * 128;
    __shared__ float As[8][64];
    __shared__ float Bs[8][128];
    const int tid = threadIdx.x;
    const int ty = tid >> 4, tx = tid & 15;
    const int lr = tid >> 1;
    const int lk = (tid & 1) * 4;

    const bool arow_ok = (tid < 128) && (m0 + lr < cnt);
    const float* aptr = g_h + ((size_t)e * CAP + m0 + lr) * R_DIM + lk;
    const float* bptr = V + ((size_t)e * D_DIM + n0 + lr) * R_DIM + lk;

    float acc[4][8];
#pragma unroll
    for (int i = 0; i < 4; i++)
#pragma unroll
        for (int j = 0; j < 8; j++) acc[i][j] = 0.0f;

    for (int k0 = 0; k0 < R_DIM; k0 += 8) {
        float4 av = make_float4(0.f, 0.f, 0.f, 0.f);
        if (arow_ok) av = *(const float4*)(aptr + k0);
        float4 bv = *(const float4*)(bptr + k0);
        __syncthreads();
        if (tid < 128) {
            As[lk + 0][lr] = av.x; As[lk + 1][lr] = av.y;
            As[lk + 2][lr] = av.z; As[lk + 3][lr] = av.w;
        }
        Bs[lk + 0][lr] = bv.x; Bs[lk + 1][lr] = bv.y;
        Bs[lk + 2][lr] = bv.z; Bs[lk + 3][lr] = bv.w;
        __syncthreads();
#pragma unroll
        for (int kk = 0; kk < 8; kk++) {
            float4 a0 = *(const float4*)&As[kk][ty * 4];
            float4 b0 = *(const float4*)&Bs[kk][tx * 8];
            float4 b1 = *(const float4*)&Bs[kk][tx * 8 + 4];
            float a[4] = {a0.x, a0.y, a0.z, a0.w};
            float b[8] = {b0.x, b0.y, b0.z, b0.w, b1.x, b1.y, b1.z, b1.w};
#pragma unroll
            for (int i = 0; i < 4; i++)
#pragma unroll
                for (int j = 0; j < 8; j++) acc[i][j] += a[i] * b[j];
        }
    }
    const float gm = gamma[e];
#pragma unroll
    for (int i = 0; i < 4; i++) {
        int m = m0 + ty * 4 + i;
        if (m < cnt) {
            int n = g_rows[e * CAP + m];
            float scale = g_w[n] * gm;
            float* dp = g_dbuf + (size_t)n * D_DIM + n0 + tx * 8;
#pragma unroll
            for (int j = 0; j < 8; j++) dp[j] = acc[i][j] * scale;
        }
    }
}

// =====================================================================
// Stage 7: combine
// =====================================================================
__global__ void __launch_bounds__(512) k_combine(float* __restrict__ y) {
    const int t = blockIdx.x;
    const int d4 = threadIdx.x;
    const float4* enc4 = (const float4*)g_enc;
    const float4* db4 = (const float4*)g_dbuf;
    float4 r = enc4[(size_t)t * 512 + d4];
    const float w0 = g_w[2 * t];
    const float w1 = g_w[2 * t + 1];
    if (w0 > 0.0f) {
        float4 a = db4[(size_t)(2 * t) * 512 + d4];
        r.x += a.x; r.y += a.y; r.z += a.z; r.w += a.w;
    }
    if (w1 > 0.0f) {
        float4 a = db4[(size_t)(2 * t + 1) * 512 + d4];
        r.x += a.x; r.y += a.y; r.z += a.z; r.w += a.w;
    }
    ((float4*)y)[(size_t)t * 512 + d4] = r;
}

// =====================================================================
extern "C" void kernel_launch(void* const* d_in, const int* in_sizes, int n_in,
                              void* d_out, int out_size) {
    const float* x     = (const float*)d_in[0];
    const float* We    = (const float*)d_in[1];
    const float* be    = (const float*)d_in[2];
    const float* Wg    = (const float*)d_in[3];
    const float* U     = (const float*)d_in[4];
    const float* V     = (const float*)d_in[5];
    const float* gamma = (const float*)d_in[6];
    float* y = (float*)d_out;

    cudaFuncSetAttribute(k_enc_mma, cudaFuncAttributeMaxDynamicSharedMemorySize, ENC_SMEM);

    dim3 gEnc(D_DIM / EB_N, B_TOK / EB_M);          // 16 x 128
    k_enc_mma<<<gEnc, 256, ENC_SMEM>>>(x, We, be);

    dim3 gLog(1, B_TOK / 128);                      // 1 x 128
    k_gemm_logits<<<gLog, 256>>>(Wg);

    k_route<<<B_TOK / 256, 256>>>();

    k_capacity<<<E_NUM, 256>>>();

    dim3 gE1(CAP / 64, E_NUM);                      // 10 x 64
    k_gemm_expert1<<<gE1, 256>>>(U);

    dim3 gE2(D_DIM / 128, CAP / 64, E_NUM);         // 16 x 10 x 64
    k_gemm_expert2<<<gE2, 256>>>(V, gamma);

    k_combine<<<B_TOK, 512>>>(y);
}

// round 4
// speedup vs baseline: 1.6283x; 1.6283x over previous
#include <cuda_runtime.h>
#include <cuda_fp16.h>
#include <math.h>
#include <stdint.h>

#define B_TOK 16384
#define D_DIM 2048
#define E_NUM 64
#define R_DIM 128
#define NASSIGN (2 * B_TOK)
#define CAP 640

// ---------------- scratch (static __device__ globals; no allocations) ----------------
__device__ float g_enc[(size_t)B_TOK * D_DIM];          // 134 MB
__device__ float g_logits[(size_t)B_TOK * E_NUM];       // 4 MB
__device__ int   g_eid[NASSIGN];
__device__ float g_w[NASSIGN];                          // weight if valid else 0
__device__ int   g_rows[E_NUM * CAP];                   // assignment ids per expert
__device__ int   g_cnt[E_NUM];
__device__ float g_h[(size_t)E_NUM * CAP * R_DIM];      // 21 MB
__device__ float g_dbuf[(size_t)NASSIGN * D_DIM];       // 268 MB

// =====================================================================
// helpers
// =====================================================================
__device__ __forceinline__ uint32_t smem_u32(const void* p) {
    uint32_t a;
    asm("{ .reg .u64 t; cvta.to.shared.u64 t, %1; cvt.u32.u64 %0, t; }" : "=r"(a) : "l"(p));
    return a;
}
__device__ __forceinline__ void sts_v4u(uint32_t addr, uint32_t a, uint32_t b, uint32_t c, uint32_t d) {
    asm volatile("st.shared.v4.b32 [%0], {%1,%2,%3,%4};"
                 :: "r"(addr), "r"(a), "r"(b), "r"(c), "r"(d) : "memory");
}
__device__ __forceinline__ void ldsm4(uint32_t* r, uint32_t addr) {
    asm volatile("ldmatrix.sync.aligned.m8n8.x4.shared.b16 {%0,%1,%2,%3}, [%4];"
                 : "=r"(r[0]), "=r"(r[1]), "=r"(r[2]), "=r"(r[3]) : "r"(addr));
}
__device__ __forceinline__ void mma_f16(float* c, const uint32_t* a, uint32_t b0, uint32_t b1) {
    asm volatile(
        "mma.sync.aligned.m16n8k16.row.col.f32.f16.f16.f32 "
        "{%0,%1,%2,%3}, {%4,%5,%6,%7}, {%8,%9}, {%0,%1,%2,%3};"
        : "+f"(c[0]), "+f"(c[1]), "+f"(c[2]), "+f"(c[3])
        : "r"(a[0]), "r"(a[1]), "r"(a[2]), "r"(a[3]), "r"(b0), "r"(b1));
}
// fp16 two-fold split of a float pair: hi = rn(x), lo = rn(x - hi)
__device__ __forceinline__ void split2(float a, float b, uint32_t& hi, uint32_t& lo) {
    __half2 h = __floats2half2_rn(a, b);
    float2 hf = __half22float2(h);
    __half2 l = __floats2half2_rn(a - hf.x, b - hf.y);
    hi = *reinterpret_cast<uint32_t*>(&h);
    lo = *reinterpret_cast<uint32_t*>(&l);
}

// =====================================================================
// Stage 1: enc = x @ We^T + be via fp16 2-fold split (3-term) mma.sync
// BM=128 BN=128 BK=32, 256 thr (8 warps: 4 x m32, 2 x n64)
// SMEM per stage: Ahi, Alo, Bhi, Blo tiles of 128 rows x 40 fp16 (80B stride)
// =====================================================================
#define SR_ROWB 80                       // bytes per smem row (40 fp16, 32 used)
#define TILE_B (128 * SR_ROWB)           // 10240
#define ST_AHI 0
#define ST_ALO TILE_B
#define ST_BHI (2 * TILE_B)
#define ST_BLO (3 * TILE_B)
#define STAGE_B (4 * TILE_B)             // 40960
#define ENC_SMEM (2 * STAGE_B)           // 81920

__global__ void __launch_bounds__(256, 1) k_enc_mma(const float* __restrict__ A,
                                                    const float* __restrict__ W,
                                                    const float* __restrict__ bias) {
    extern __shared__ char smraw[];
    const uint32_t sb = smem_u32(smraw);
    const int tid = threadIdx.x;
    const int lane = tid & 31;
    const int wid = tid >> 5;
    const int wm = wid & 3;              // m offset 32 each
    const int wn = wid >> 2;             // n offset 64 each
    const int m0 = blockIdx.y * 128;
    const int n0 = blockIdx.x * 128;

    // ---- loader mapping: 256 threads cover 128 rows x 32 cols (16 floats each)
    const int lrow = tid >> 1;
    const int cseg = tid & 1;            // 0/1 -> cols 0-15 / 16-31
    const float* aG = A + (size_t)(m0 + lrow) * D_DIM + cseg * 16;
    const float* bG = W + (size_t)(n0 + lrow) * D_DIM + cseg * 16;
    const uint32_t stoff = (uint32_t)(lrow * SR_ROWB + cseg * 32);

    // ---- fragment base offsets (within a tile)
    const uint32_t aFrag = (uint32_t)((wm * 32 + (lane & 15)) * SR_ROWB) + (uint32_t)((lane >> 4) * 16);
    const uint32_t bFrag = (uint32_t)((wn * 64 + (lane & 7)) * SR_ROWB) + (uint32_t)((lane >> 3) * 16);

    float acc[2][8][4];
#pragma unroll
    for (int i = 0; i < 2; i++)
#pragma unroll
        for (int j = 0; j < 8; j++)
#pragma unroll
            for (int q = 0; q < 4; q++) acc[i][j][q] = 0.0f;

    float4 ra[4], rb[4];
    const int NC = D_DIM / 32;           // 64

    // ---- prologue: chunk 0 -> stage 0
#pragma unroll
    for (int j = 0; j < 4; j++) {
        ra[j] = *(const float4*)(aG + j * 4);
        rb[j] = *(const float4*)(bG + j * 4);
    }
    {
        const uint32_t stg = sb;
        uint32_t h[8], l[8];
#pragma unroll
        for (int j = 0; j < 4; j++) {
            split2(ra[j].x, ra[j].y, h[2 * j], l[2 * j]);
            split2(ra[j].z, ra[j].w, h[2 * j + 1], l[2 * j + 1]);
        }
        sts_v4u(stg + ST_AHI + stoff,      h[0], h[1], h[2], h[3]);
        sts_v4u(stg + ST_AHI + stoff + 16, h[4], h[5], h[6], h[7]);
        sts_v4u(stg + ST_ALO + stoff,      l[0], l[1], l[2], l[3]);
        sts_v4u(stg + ST_ALO + stoff + 16, l[4], l[5], l[6], l[7]);
#pragma unroll
        for (int j = 0; j < 4; j++) {
            split2(rb[j].x, rb[j].y, h[2 * j], l[2 * j]);
            split2(rb[j].z, rb[j].w, h[2 * j + 1], l[2 * j + 1]);
        }
        sts_v4u(stg + ST_BHI + stoff,      h[0], h[1], h[2], h[3]);
        sts_v4u(stg + ST_BHI + stoff + 16, h[4], h[5], h[6], h[7]);
        sts_v4u(stg + ST_BLO + stoff,      l[0], l[1], l[2], l[3]);
        sts_v4u(stg + ST_BLO + stoff + 16, l[4], l[5], l[6], l[7]);
    }
    __syncthreads();

#pragma unroll 1
    for (int c = 0; c < NC; c++) {
        // prefetch next chunk to regs
        if (c + 1 < NC) {
            const int koff = (c + 1) * 32;
#pragma unroll
            for (int j = 0; j < 4; j++) {
                ra[j] = *(const float4*)(aG + koff + j * 4);
                rb[j] = *(const float4*)(bG + koff + j * 4);
            }
        }
        // ---- compute on stage c&1
        const uint32_t stg = sb + (uint32_t)(c & 1) * STAGE_B;
        uint32_t AH[2][2][4], AL[2][2][4];
#pragma unroll
        for (int mi = 0; mi < 2; mi++)
#pragma unroll
            for (int kf = 0; kf < 2; kf++) {
                const uint32_t off = aFrag + (uint32_t)(mi * 16 * SR_ROWB) + (uint32_t)(kf * 32);
                ldsm4(AH[mi][kf], stg + ST_AHI + off);
                ldsm4(AL[mi][kf], stg + ST_ALO + off);
            }
#pragma unroll
        for (int ni = 0; ni < 8; ni++) {
            uint32_t BH[4], BL[4];
            const uint32_t boff = bFrag + (uint32_t)(ni * 8 * SR_ROWB);
            ldsm4(BH, stg + ST_BHI + boff);
            ldsm4(BL, stg + ST_BLO + boff);
#pragma unroll
            for (int mi = 0; mi < 2; mi++) {
                mma_f16(acc[mi][ni], AH[mi][0], BH[0], BH[1]);
                mma_f16(acc[mi][ni], AH[mi][1], BH[2], BH[3]);
                mma_f16(acc[mi][ni], AH[mi][0], BL[0], BL[1]);
                mma_f16(acc[mi][ni], AH[mi][1], BL[2], BL[3]);
                mma_f16(acc[mi][ni], AL[mi][0], BH[0], BH[1]);
                mma_f16(acc[mi][ni], AL[mi][1], BH[2], BH[3]);
            }
        }
        // ---- store next chunk into the other stage
        if (c + 1 < NC) {
            const uint32_t stg2 = sb + (uint32_t)((c + 1) & 1) * STAGE_B;
            uint32_t h[8], l[8];
#pragma unroll
            for (int j = 0; j < 4; j++) {
                split2(ra[j].x, ra[j].y, h[2 * j], l[2 * j]);
                split2(ra[j].z, ra[j].w, h[2 * j + 1], l[2 * j + 1]);
            }
            sts_v4u(stg2 + ST_AHI + stoff,      h[0], h[1], h[2], h[3]);
            sts_v4u(stg2 + ST_AHI + stoff + 16, h[4], h[5], h[6], h[7]);
            sts_v4u(stg2 + ST_ALO + stoff,      l[0], l[1], l[2], l[3]);
            sts_v4u(stg2 + ST_ALO + stoff + 16, l[4], l[5], l[6], l[7]);
#pragma unroll
            for (int j = 0; j < 4; j++) {
                split2(rb[j].x, rb[j].y, h[2 * j], l[2 * j]);
                split2(rb[j].z, rb[j].w, h[2 * j + 1], l[2 * j + 1]);
            }
            sts_v4u(stg2 + ST_BHI + stoff,      h[0], h[1], h[2], h[3]);
            sts_v4u(stg2 + ST_BHI + stoff + 16, h[4], h[5], h[6], h[7]);
            sts_v4u(stg2 + ST_BLO + stoff,      l[0], l[1], l[2], l[3]);
            sts_v4u(stg2 + ST_BLO + stoff + 16, l[4], l[5], l[6], l[7]);
            __syncthreads();
        }
    }

    // ---- epilogue: add bias, store
    const int g = lane >> 2;
    const int t = lane & 3;
#pragma unroll
    for (int mi = 0; mi < 2; mi++) {
        const int r0 = m0 + wm * 32 + mi * 16 + g;
        const int r1 = r0 + 8;
#pragma unroll
        for (int ni = 0; ni < 8; ni++) {
            const int col = n0 + wn * 64 + ni * 8 + 2 * t;
            const float2 bv = *(const float2*)(bias + col);
            float2 o0, o1;
            o0.x = acc[mi][ni][0] + bv.x; o0.y = acc[mi][ni][1] + bv.y;
            o1.x = acc[mi][ni][2] + bv.x; o1.y = acc[mi][ni][3] + bv.y;
            *(float2*)(g_enc + (size_t)r0 * D_DIM + col) = o0;
            *(float2*)(g_enc + (size_t)r1 * D_DIM + col) = o1;
        }
    }
}

// =====================================================================
// Stage 2: logits = enc @ Wg^T  (M=16384, N=64, K=2048, fp32 SIMT)
// =====================================================================
__global__ void __launch_bounds__(256) k_gemm_logits(const float* __restrict__ Wg) {
    __shared__ float As[8][128];
    __shared__ float Bs[8][64];
    const int tid = threadIdx.x;
    const int m0 = blockIdx.y * 128;
    const int ty = tid >> 4, tx = tid & 15;
    const int lr = tid >> 1;
    const int lk = (tid & 1) * 4;
    const float* aptr = g_enc + (size_t)(m0 + lr) * D_DIM + lk;
    const float* bptr = Wg + (size_t)(tid >> 1) * D_DIM + lk;

    float acc[8][4];
#pragma unroll
    for (int i = 0; i < 8; i++)
#pragma unroll
        for (int j = 0; j < 4; j++) acc[i][j] = 0.0f;

    for (int k0 = 0; k0 < D_DIM; k0 += 8) {
        float4 av = *(const float4*)(aptr + k0);
        float4 bv = make_float4(0.f, 0.f, 0.f, 0.f);
        if (tid < 128) bv = *(const float4*)(bptr + k0);
        __syncthreads();
        As[lk + 0][lr] = av.x; As[lk + 1][lr] = av.y;
        As[lk + 2][lr] = av.z; As[lk + 3][lr] = av.w;
        if (tid < 128) {
            Bs[lk + 0][lr] = bv.x; Bs[lk + 1][lr] = bv.y;
            Bs[lk + 2][lr] = bv.z; Bs[lk + 3][lr] = bv.w;
        }
        __syncthreads();
#pragma unroll
        for (int kk = 0; kk < 8; kk++) {
            float4 a0 = *(const float4*)&As[kk][ty * 8];
            float4 a1 = *(const float4*)&As[kk][ty * 8 + 4];
            float4 b0 = *(const float4*)&Bs[kk][tx * 4];
            float a[8] = {a0.x, a0.y, a0.z, a0.w, a1.x, a1.y, a1.z, a1.w};
            float b[4] = {b0.x, b0.y, b0.z, b0.w};
#pragma unroll
            for (int i = 0; i < 8; i++)
#pragma unroll
                for (int j = 0; j < 4; j++) acc[i][j] += a[i] * b[j];
        }
    }
#pragma unroll
    for (int i = 0; i < 8; i++)
#pragma unroll
        for (int j = 0; j < 4; j++)
            g_logits[(size_t)(m0 + ty * 8 + i) * E_NUM + tx * 4 + j] = acc[i][j];
}

// =====================================================================
// Stage 3: per-token top-2 + masked softmax
// =====================================================================
__global__ void __launch_bounds__(256) k_route() {
    const int t = blockIdx.x * blockDim.x + threadIdx.x;
    if (t >= B_TOK) return;
    const float* lg = g_logits + (size_t)t * E_NUM;
    float v0 = -INFINITY; int i0 = 0;
#pragma unroll 8
    for (int e = 0; e < E_NUM; e++) {
        float v = lg[e];
        if (v > v0) { v0 = v; i0 = e; }
    }
    float v1 = -INFINITY; int i1 = 0;
#pragma unroll 8
    for (int e = 0; e < E_NUM; e++) {
        if (e == i0) continue;
        float v = lg[e];
        if (v > v1) { v1 = v; i1 = e; }
    }
    float e1 = expf(v1 - v0);
    float s = 1.0f + e1 + 1e-12f;
    float w0 = 1.0f / s;
    float w1 = e1 / s;
    g_eid[2 * t]     = i0;
    g_eid[2 * t + 1] = i1;
    g_w[2 * t]       = (w0 > 1e-12f) ? w0 : 0.0f;
    g_w[2 * t + 1]   = (w1 > 1e-12f) ? w1 : 0.0f;
}

// =====================================================================
// Stage 4: deterministic capacity scan
// =====================================================================
__global__ void __launch_bounds__(256) k_capacity() {
    const int e = blockIdx.x;
    const int tid = threadIdx.x;
    const int lane = tid & 31;
    const int wrp = tid >> 5;
    __shared__ int warp_cnt[8];
    int base = 0;
    for (int n0 = 0; n0 < NASSIGN; n0 += 256) {
        const int n = n0 + tid;
        const bool flag = (g_eid[n] == e) && (g_w[n] > 0.0f);
        unsigned m = __ballot_sync(0xffffffffu, flag);
        if (lane == 0) warp_cnt[wrp] = __popc(m);
        __syncthreads();
        int off = 0, tot = 0;
#pragma unroll
        for (int i = 0; i < 8; i++) {
            int c = warp_cnt[i];
            if (i < wrp) off += c;
            tot += c;
        }
        if (flag) {
            int pos = base + off + __popc(m & ((1u << lane) - 1u));
            if (pos < CAP) g_rows[e * CAP + pos] = n;
            else           g_w[n] = 0.0f;
        }
        base += tot;
        __syncthreads();
    }
    if (tid == 0) g_cnt[e] = (base < CAP) ? base : CAP;
}

// =====================================================================
// Stage 5: H = silu(X_gathered @ U_e^T)
// =====================================================================
__device__ __forceinline__ float silu_f(float v) {
    return v / (1.0f + expf(-v));
}

__global__ void __launch_bounds__(256) k_gemm_expert1(const float* __restrict__ U) {
    const int e = blockIdx.y;
    const int cnt = g_cnt[e];
    const int m0 = blockIdx.x * 64;
    if (m0 >= cnt) return;
    __shared__ float As[8][64];
    __shared__ float Bs[8][128];
    const int tid = threadIdx.x;
    const int ty = tid >> 4, tx = tid & 15;
    const int lr = tid >> 1;
    const int lk = (tid & 1) * 4;

    int atok = -1;
    if (tid < 128) {
        if (m0 + lr < cnt) atok = g_rows[e * CAP + m0 + lr] >> 1;
    }
    const float* aptr = (atok >= 0) ? (g_enc + (size_t)atok * D_DIM + lk) : g_enc;
    const float* bptr = U + ((size_t)e * R_DIM + lr) * D_DIM + lk;

    float acc[4][8];
#pragma unroll
    for (int i = 0; i < 4; i++)
#pragma unroll
        for (int j = 0; j < 8; j++) acc[i][j] = 0.0f;

    for (int k0 = 0; k0 < D_DIM; k0 += 8) {
        float4 av = make_float4(0.f, 0.f, 0.f, 0.f);
        if (atok >= 0) av = *(const float4*)(aptr + k0);
        float4 bv = *(const float4*)(bptr + k0);
        __syncthreads();
        if (tid < 128) {
            As[lk + 0][lr] = av.x; As[lk + 1][lr] = av.y;
            As[lk + 2][lr] = av.z; As[lk + 3][lr] = av.w;
        }
        Bs[lk + 0][lr] = bv.x; Bs[lk + 1][lr] = bv.y;
        Bs[lk + 2][lr] = bv.z; Bs[lk + 3][lr] = bv.w;
        __syncthreads();
#pragma unroll
        for (int kk = 0; kk < 8; kk++) {
            float4 a0 = *(const float4*)&As[kk][ty * 4];
            float4 b0 = *(const float4*)&Bs[kk][tx * 8];
            float4 b1 = *(const float4*)&Bs[kk][tx * 8 + 4];
            float a[4] = {a0.x, a0.y, a0.z, a0.w};
            float b[8] = {b0.x, b0.y, b0.z, b0.w, b1.x, b1.y, b1.z, b1.w};
#pragma unroll
            for (int i = 0; i < 4; i++)
#pragma unroll
                for (int j = 0; j < 8; j++) acc[i][j] += a[i] * b[j];
        }
    }
#pragma unroll
    for (int i = 0; i < 4; i++) {
        int m = m0 + ty * 4 + i;
        if (m < cnt) {
            float* hp = g_h + ((size_t)e * CAP + m) * R_DIM + tx * 8;
#pragma unroll
            for (int j = 0; j < 8; j++) hp[j] = silu_f(acc[i][j]);
        }
    }
}

// =====================================================================
// Stage 6: dbuf[n] = (w * gamma_e) * (H @ V_e^T)
// =====================================================================
__global__ void __launch_bounds__(256) k_gemm_expert2(const float* __restrict__ V,
                                                      const float* __restrict__ gamma) {
    const int e = blockIdx.z;
    const int cnt = g_cnt[e];
    const int m0 = blockIdx.y * 64;
    if (m0 >= cnt) return;
    const int n0 = blockIdx.x * 128;
    __shared__ float As[8][64];
    __shared__ float Bs[8][128];
    const int tid = threadIdx.x;
    const int ty = tid >> 4, tx = tid & 15;
    const int lr = tid >> 1;
    const int lk = (tid & 1) * 4;

    const bool arow_ok = (tid < 128) && (m0 + lr < cnt);
    const float* aptr = g_h + ((size_t)e * CAP + m0 + lr) * R_DIM + lk;
    const float* bptr = V + ((size_t)e * D_DIM + n0 + lr) * R_DIM + lk;

    float acc[4][8];
#pragma unroll
    for (int i = 0; i < 4; i++)
#pragma unroll
        for (int j = 0; j < 8; j++) acc[i][j] = 0.0f;

    for (int k0 = 0; k0 < R_DIM; k0 += 8) {
        float4 av = make_float4(0.f, 0.f, 0.f, 0.f);
        if (arow_ok) av = *(const float4*)(aptr + k0);
        float4 bv = *(const float4*)(bptr + k0);
        __syncthreads();
        if (tid < 128) {
            As[lk + 0][lr] = av.x; As[lk + 1][lr] = av.y;
            As[lk + 2][lr] = av.z; As[lk + 3][lr] = av.w;
        }
        Bs[lk + 0][lr] = bv.x; Bs[lk + 1][lr] = bv.y;
        Bs[lk + 2][lr] = bv.z; Bs[lk + 3][lr] = bv.w;
        __syncthreads();
#pragma unroll
        for (int kk = 0; kk < 8; kk++) {
            float4 a0 = *(const float4*)&As[kk][ty * 4];
            float4 b0 = *(const float4*)&Bs[kk][tx * 8];
            float4 b1 = *(const float4*)&Bs[kk][tx * 8 + 4];
            float a[4] = {a0.x, a0.y, a0.z, a0.w};
            float b[8] = {b0.x, b0.y, b0.z, b0.w, b1.x, b1.y, b1.z, b1.w};
#pragma unroll
            for (int i = 0; i < 4; i++)
#pragma unroll
                for (int j = 0; j < 8; j++) acc[i][j] += a[i] * b[j];
        }
    }
    const float gm = gamma[e];
#pragma unroll
    for (int i = 0; i < 4; i++) {
        int m = m0 + ty * 4 + i;
        if (m < cnt) {
            int n = g_rows[e * CAP + m];
            float scale = g_w[n] * gm;
            float* dp = g_dbuf + (size_t)n * D_DIM + n0 + tx * 8;
#pragma unroll
            for (int j = 0; j < 8; j++) dp[j] = acc[i][j] * scale;
        }
    }
}

// =====================================================================
// Stage 7: combine
// =====================================================================
__global__ void __launch_bounds__(512) k_combine(float* __restrict__ y) {
    const int t = blockIdx.x;
    const int d4 = threadIdx.x;
    const float4* enc4 = (const float4*)g_enc;
    const float4* db4 = (const float4*)g_dbuf;
    float4 r = enc4[(size_t)t * 512 + d4];
    const float w0 = g_w[2 * t];
    const float w1 = g_w[2 * t + 1];
    if (w0 > 0.0f) {
        float4 a = db4[(size_t)(2 * t) * 512 + d4];
        r.x += a.x; r.y += a.y; r.z += a.z; r.w += a.w;
    }
    if (w1 > 0.0f) {
        float4 a = db4[(size_t)(2 * t + 1) * 512 + d4];
        r.x += a.x; r.y += a.y; r.z += a.z; r.w += a.w;
    }
    ((float4*)y)[(size_t)t * 512 + d4] = r;
}

// =====================================================================
extern "C" void kernel_launch(void* const* d_in, const int* in_sizes, int n_in,
                              void* d_out, int out_size) {
    const float* x     = (const float*)d_in[0];
    const float* We    = (const float*)d_in[1];
    const float* be    = (const float*)d_in[2];
    const float* Wg    = (const float*)d_in[3];
    const float* U     = (const float*)d_in[4];
    const float* V     = (const float*)d_in[5];
    const float* gamma = (const float*)d_in[6];
    float* y = (float*)d_out;

    cudaFuncSetAttribute(k_enc_mma, cudaFuncAttributeMaxDynamicSharedMemorySize, ENC_SMEM);

    dim3 gEnc(D_DIM / 128, B_TOK / 128);            // 16 x 128
    k_enc_mma<<<gEnc, 256, ENC_SMEM>>>(x, We, be);

    dim3 gLog(1, B_TOK / 128);                      // 1 x 128
    k_gemm_logits<<<gLog, 256>>>(Wg);

    k_route<<<B_TOK / 256, 256>>>();

    k_capacity<<<E_NUM, 256>>>();

    dim3 gE1(CAP / 64, E_NUM);                      // 10 x 64
    k_gemm_expert1<<<gE1, 256>>>(U);

    dim3 gE2(D_DIM / 128, CAP / 64, E_NUM);         // 16 x 10 x 64
    k_gemm_expert2<<<gE2, 256>>>(V, gamma);

    k_combine<<<B_TOK, 512>>>(y);
}

// round 5
// speedup vs baseline: 2.2470x; 1.3800x over previous
#include <cuda_runtime.h>
#include <cuda_fp16.h>
#include <math.h>
#include <stdint.h>

#define B_TOK 16384
#define D_DIM 2048
#define E_NUM 64
#define R_DIM 128
#define NASSIGN (2 * B_TOK)
#define CAP 640

// ---------------- scratch (static __device__ globals; no allocations) ----------------
__device__ float g_enc[(size_t)B_TOK * D_DIM];          // 134 MB
__device__ float g_logits[(size_t)B_TOK * E_NUM];       // 4 MB
__device__ int   g_eid[NASSIGN];
__device__ float g_w[NASSIGN];                          // weight if valid else 0
__device__ int   g_rows[E_NUM * CAP];                   // assignment ids per expert
__device__ int   g_cnt[E_NUM];
__device__ float g_h[(size_t)E_NUM * CAP * R_DIM];      // 21 MB
__device__ float g_dbuf[(size_t)NASSIGN * D_DIM];       // 268 MB

// =====================================================================
// helpers
// =====================================================================
__device__ __forceinline__ uint32_t smem_u32(const void* p) {
    uint32_t a;
    asm("{ .reg .u64 t; cvta.to.shared.u64 t, %1; cvt.u32.u64 %0, t; }" : "=r"(a) : "l"(p));
    return a;
}
__device__ __forceinline__ void sts_v4u(uint32_t addr, uint32_t a, uint32_t b, uint32_t c, uint32_t d) {
    asm volatile("st.shared.v4.b32 [%0], {%1,%2,%3,%4};"
                 :: "r"(addr), "r"(a), "r"(b), "r"(c), "r"(d) : "memory");
}
__device__ __forceinline__ void ldsm4(uint32_t* r, uint32_t addr) {
    asm volatile("ldmatrix.sync.aligned.m8n8.x4.shared.b16 {%0,%1,%2,%3}, [%4];"
                 : "=r"(r[0]), "=r"(r[1]), "=r"(r[2]), "=r"(r[3]) : "r"(addr));
}
__device__ __forceinline__ void mma_f16(float* c, const uint32_t* a, uint32_t b0, uint32_t b1) {
    asm volatile(
        "mma.sync.aligned.m16n8k16.row.col.f32.f16.f16.f32 "
        "{%0,%1,%2,%3}, {%4,%5,%6,%7}, {%8,%9}, {%0,%1,%2,%3};"
        : "+f"(c[0]), "+f"(c[1]), "+f"(c[2]), "+f"(c[3])
        : "r"(a[0]), "r"(a[1]), "r"(a[2]), "r"(a[3]), "r"(b0), "r"(b1));
}
// fp16 two-fold split of a float pair: hi = rn(x), lo = rn(x - hi)
__device__ __forceinline__ void split2(float a, float b, uint32_t& hi, uint32_t& lo) {
    __half2 h = __floats2half2_rn(a, b);
    float2 hf = __half22float2(h);
    __half2 l = __floats2half2_rn(a - hf.x, b - hf.y);
    hi = *reinterpret_cast<uint32_t*>(&h);
    lo = *reinterpret_cast<uint32_t*>(&l);
}
__device__ __forceinline__ float silu_f(float v) {
    return v / (1.0f + expf(-v));
}

#define SR_ROWB 80                       // bytes per smem row (40 fp16, 32 used)

// =====================================================================
// Stage 1: enc = x @ We^T + be via fp16 2-fold split (3-term) mma.sync
// BM=128 BN=128 BK=32, 256 thr (8 warps: 4 x m32, 2 x n64)
// =====================================================================
#define TILE_B (128 * SR_ROWB)           // 10240
#define ST_AHI 0
#define ST_ALO TILE_B
#define ST_BHI (2 * TILE_B)
#define ST_BLO (3 * TILE_B)
#define STAGE_B (4 * TILE_B)             // 40960
#define ENC_SMEM (2 * STAGE_B)           // 81920

__global__ void __launch_bounds__(256, 1) k_enc_mma(const float* __restrict__ A,
                                                    const float* __restrict__ W,
                                                    const float* __restrict__ bias) {
    extern __shared__ char smraw[];
    const uint32_t sb = smem_u32(smraw);
    const int tid = threadIdx.x;
    const int lane = tid & 31;
    const int wid = tid >> 5;
    const int wm = wid & 3;
    const int wn = wid >> 2;
    const int m0 = blockIdx.y * 128;
    const int n0 = blockIdx.x * 128;

    const int lrow = tid >> 1;
    const int cseg = tid & 1;
    const float* aG = A + (size_t)(m0 + lrow) * D_DIM + cseg * 16;
    const float* bG = W + (size_t)(n0 + lrow) * D_DIM + cseg * 16;
    const uint32_t stoff = (uint32_t)(lrow * SR_ROWB + cseg * 32);

    const uint32_t aFrag = (uint32_t)((wm * 32 + (lane & 15)) * SR_ROWB) + (uint32_t)((lane >> 4) * 16);
    const uint32_t bFrag = (uint32_t)((wn * 64 + (lane & 7)) * SR_ROWB) + (uint32_t)((lane >> 3) * 16);

    float acc[2][8][4];
#pragma unroll
    for (int i = 0; i < 2; i++)
#pragma unroll
        for (int j = 0; j < 8; j++)
#pragma unroll
            for (int q = 0; q < 4; q++) acc[i][j][q] = 0.0f;

    float4 ra[4], rb[4];
    const int NC = D_DIM / 32;

#pragma unroll
    for (int j = 0; j < 4; j++) {
        ra[j] = *(const float4*)(aG + j * 4);
        rb[j] = *(const float4*)(bG + j * 4);
    }
    {
        const uint32_t stg = sb;
        uint32_t h[8], l[8];
#pragma unroll
        for (int j = 0; j < 4; j++) {
            split2(ra[j].x, ra[j].y, h[2 * j], l[2 * j]);
            split2(ra[j].z, ra[j].w, h[2 * j + 1], l[2 * j + 1]);
        }
        sts_v4u(stg + ST_AHI + stoff,      h[0], h[1], h[2], h[3]);
        sts_v4u(stg + ST_AHI + stoff + 16, h[4], h[5], h[6], h[7]);
        sts_v4u(stg + ST_ALO + stoff,      l[0], l[1], l[2], l[3]);
        sts_v4u(stg + ST_ALO + stoff + 16, l[4], l[5], l[6], l[7]);
#pragma unroll
        for (int j = 0; j < 4; j++) {
            split2(rb[j].x, rb[j].y, h[2 * j], l[2 * j]);
            split2(rb[j].z, rb[j].w, h[2 * j + 1], l[2 * j + 1]);
        }
        sts_v4u(stg + ST_BHI + stoff,      h[0], h[1], h[2], h[3]);
        sts_v4u(stg + ST_BHI + stoff + 16, h[4], h[5], h[6], h[7]);
        sts_v4u(stg + ST_BLO + stoff,      l[0], l[1], l[2], l[3]);
        sts_v4u(stg + ST_BLO + stoff + 16, l[4], l[5], l[6], l[7]);
    }
    __syncthreads();

#pragma unroll 1
    for (int c = 0; c < NC; c++) {
        if (c + 1 < NC) {
            const int koff = (c + 1) * 32;
#pragma unroll
            for (int j = 0; j < 4; j++) {
                ra[j] = *(const float4*)(aG + koff + j * 4);
                rb[j] = *(const float4*)(bG + koff + j * 4);
            }
        }
        const uint32_t stg = sb + (uint32_t)(c & 1) * STAGE_B;
        uint32_t AH[2][2][4], AL[2][2][4];
#pragma unroll
        for (int mi = 0; mi < 2; mi++)
#pragma unroll
            for (int kf = 0; kf < 2; kf++) {
                const uint32_t off = aFrag + (uint32_t)(mi * 16 * SR_ROWB) + (uint32_t)(kf * 32);
                ldsm4(AH[mi][kf], stg + ST_AHI + off);
                ldsm4(AL[mi][kf], stg + ST_ALO + off);
            }
#pragma unroll
        for (int ni = 0; ni < 8; ni++) {
            uint32_t BH[4], BL[4];
            const uint32_t boff = bFrag + (uint32_t)(ni * 8 * SR_ROWB);
            ldsm4(BH, stg + ST_BHI + boff);
            ldsm4(BL, stg + ST_BLO + boff);
#pragma unroll
            for (int mi = 0; mi < 2; mi++) {
                mma_f16(acc[mi][ni], AH[mi][0], BH[0], BH[1]);
                mma_f16(acc[mi][ni], AH[mi][1], BH[2], BH[3]);
                mma_f16(acc[mi][ni], AH[mi][0], BL[0], BL[1]);
                mma_f16(acc[mi][ni], AH[mi][1], BL[2], BL[3]);
                mma_f16(acc[mi][ni], AL[mi][0], BH[0], BH[1]);
                mma_f16(acc[mi][ni], AL[mi][1], BH[2], BH[3]);
            }
        }
        if (c + 1 < NC) {
            const uint32_t stg2 = sb + (uint32_t)((c + 1) & 1) * STAGE_B;
            uint32_t h[8], l[8];
#pragma unroll
            for (int j = 0; j < 4; j++) {
                split2(ra[j].x, ra[j].y, h[2 * j], l[2 * j]);
                split2(ra[j].z, ra[j].w, h[2 * j + 1], l[2 * j + 1]);
            }
            sts_v4u(stg2 + ST_AHI + stoff,      h[0], h[1], h[2], h[3]);
            sts_v4u(stg2 + ST_AHI + stoff + 16, h[4], h[5], h[6], h[7]);
            sts_v4u(stg2 + ST_ALO + stoff,      l[0], l[1], l[2], l[3]);
            sts_v4u(stg2 + ST_ALO + stoff + 16, l[4], l[5], l[6], l[7]);
#pragma unroll
            for (int j = 0; j < 4; j++) {
                split2(rb[j].x, rb[j].y, h[2 * j], l[2 * j]);
                split2(rb[j].z, rb[j].w, h[2 * j + 1], l[2 * j + 1]);
            }
            sts_v4u(stg2 + ST_BHI + stoff,      h[0], h[1], h[2], h[3]);
            sts_v4u(stg2 + ST_BHI + stoff + 16, h[4], h[5], h[6], h[7]);
            sts_v4u(stg2 + ST_BLO + stoff,      l[0], l[1], l[2], l[3]);
            sts_v4u(stg2 + ST_BLO + stoff + 16, l[4], l[5], l[6], l[7]);
            __syncthreads();
        }
    }

    const int g = lane >> 2;
    const int t = lane & 3;
#pragma unroll
    for (int mi = 0; mi < 2; mi++) {
        const int r0 = m0 + wm * 32 + mi * 16 + g;
        const int r1 = r0 + 8;
#pragma unroll
        for (int ni = 0; ni < 8; ni++) {
            const int col = n0 + wn * 64 + ni * 8 + 2 * t;
            const float2 bv = *(const float2*)(bias + col);
            float2 o0, o1;
            o0.x = acc[mi][ni][0] + bv.x; o0.y = acc[mi][ni][1] + bv.y;
            o1.x = acc[mi][ni][2] + bv.x; o1.y = acc[mi][ni][3] + bv.y;
            *(float2*)(g_enc + (size_t)r0 * D_DIM + col) = o0;
            *(float2*)(g_enc + (size_t)r1 * D_DIM + col) = o1;
        }
    }
}

// =====================================================================
// Stage 2: logits = enc @ Wg^T  (fp32 SIMT — exact, routing-critical)
// =====================================================================
__global__ void __launch_bounds__(256) k_gemm_logits(const float* __restrict__ Wg) {
    __shared__ float As[8][128];
    __shared__ float Bs[8][64];
    const int tid = threadIdx.x;
    const int m0 = blockIdx.y * 128;
    const int ty = tid >> 4, tx = tid & 15;
    const int lr = tid >> 1;
    const int lk = (tid & 1) * 4;
    const float* aptr = g_enc + (size_t)(m0 + lr) * D_DIM + lk;
    const float* bptr = Wg + (size_t)(tid >> 1) * D_DIM + lk;

    float acc[8][4];
#pragma unroll
    for (int i = 0; i < 8; i++)
#pragma unroll
        for (int j = 0; j < 4; j++) acc[i][j] = 0.0f;

    for (int k0 = 0; k0 < D_DIM; k0 += 8) {
        float4 av = *(const float4*)(aptr + k0);
        float4 bv = make_float4(0.f, 0.f, 0.f, 0.f);
        if (tid < 128) bv = *(const float4*)(bptr + k0);
        __syncthreads();
        As[lk + 0][lr] = av.x; As[lk + 1][lr] = av.y;
        As[lk + 2][lr] = av.z; As[lk + 3][lr] = av.w;
        if (tid < 128) {
            Bs[lk + 0][lr] = bv.x; Bs[lk + 1][lr] = bv.y;
            Bs[lk + 2][lr] = bv.z; Bs[lk + 3][lr] = bv.w;
        }
        __syncthreads();
#pragma unroll
        for (int kk = 0; kk < 8; kk++) {
            float4 a0 = *(const float4*)&As[kk][ty * 8];
            float4 a1 = *(const float4*)&As[kk][ty * 8 + 4];
            float4 b0 = *(const float4*)&Bs[kk][tx * 4];
            float a[8] = {a0.x, a0.y, a0.z, a0.w, a1.x, a1.y, a1.z, a1.w};
            float b[4] = {b0.x, b0.y, b0.z, b0.w};
#pragma unroll
            for (int i = 0; i < 8; i++)
#pragma unroll
                for (int j = 0; j < 4; j++) acc[i][j] += a[i] * b[j];
        }
    }
#pragma unroll
    for (int i = 0; i < 8; i++)
#pragma unroll
        for (int j = 0; j < 4; j++)
            g_logits[(size_t)(m0 + ty * 8 + i) * E_NUM + tx * 4 + j] = acc[i][j];
}

// =====================================================================
// Stage 3: per-token top-2 + masked softmax
// =====================================================================
__global__ void __launch_bounds__(256) k_route() {
    const int t = blockIdx.x * blockDim.x + threadIdx.x;
    if (t >= B_TOK) return;
    const float* lg = g_logits + (size_t)t * E_NUM;
    float v0 = -INFINITY; int i0 = 0;
#pragma unroll 8
    for (int e = 0; e < E_NUM; e++) {
        float v = lg[e];
        if (v > v0) { v0 = v; i0 = e; }
    }
    float v1 = -INFINITY; int i1 = 0;
#pragma unroll 8
    for (int e = 0; e < E_NUM; e++) {
        if (e == i0) continue;
        float v = lg[e];
        if (v > v1) { v1 = v; i1 = e; }
    }
    float e1 = expf(v1 - v0);
    float s = 1.0f + e1 + 1e-12f;
    float w0 = 1.0f / s;
    float w1 = e1 / s;
    g_eid[2 * t]     = i0;
    g_eid[2 * t + 1] = i1;
    g_w[2 * t]       = (w0 > 1e-12f) ? w0 : 0.0f;
    g_w[2 * t + 1]   = (w1 > 1e-12f) ? w1 : 0.0f;
}

// =====================================================================
// Stage 4: deterministic capacity scan
// =====================================================================
__global__ void __launch_bounds__(256) k_capacity() {
    const int e = blockIdx.x;
    const int tid = threadIdx.x;
    const int lane = tid & 31;
    const int wrp = tid >> 5;
    __shared__ int warp_cnt[8];
    int base = 0;
    for (int n0 = 0; n0 < NASSIGN; n0 += 256) {
        const int n = n0 + tid;
        const bool flag = (g_eid[n] == e) && (g_w[n] > 0.0f);
        unsigned m = __ballot_sync(0xffffffffu, flag);
        if (lane == 0) warp_cnt[wrp] = __popc(m);
        __syncthreads();
        int off = 0, tot = 0;
#pragma unroll
        for (int i = 0; i < 8; i++) {
            int c = warp_cnt[i];
            if (i < wrp) off += c;
            tot += c;
        }
        if (flag) {
            int pos = base + off + __popc(m & ((1u << lane) - 1u));
            if (pos < CAP) g_rows[e * CAP + pos] = n;
            else           g_w[n] = 0.0f;
        }
        base += tot;
        __syncthreads();
    }
    if (tid == 0) g_cnt[e] = (base < CAP) ? base : CAP;
}

// =====================================================================
// Stage 5: H = silu(Xg @ U_e^T) via fp16-split mma
// BM=64, BN=128(R), BK=32, NC=64; 8 warps: 2(m32) x 4(n32)
// =====================================================================
#define E1_AB (64 * SR_ROWB)             // 5120
#define E1_BB (128 * SR_ROWB)            // 10240
#define E1_AHI 0
#define E1_ALO E1_AB
#define E1_BHI (2 * E1_AB)
#define E1_BLO (2 * E1_AB + E1_BB)
#define E1_STAGE (2 * E1_AB + 2 * E1_BB) // 30720
#define E1_SMEM (2 * E1_STAGE)           // 61440

__global__ void __launch_bounds__(256, 1) k_exp1_mma(const float* __restrict__ U) {
    const int e = blockIdx.y;
    const int cnt = g_cnt[e];
    const int m0 = blockIdx.x * 64;
    if (m0 >= cnt) return;
    extern __shared__ char smraw[];
    const uint32_t sb = smem_u32(smraw);
    const int tid = threadIdx.x;
    const int lane = tid & 31;
    const int wid = tid >> 5;
    const int wm = wid & 1;
    const int wn = wid >> 1;

    // B loader: all 256 threads, rows of U[e] (128 x 32 per chunk)
    const int lrow = tid >> 1;
    const int cseg = tid & 1;
    const float* bG = U + ((size_t)e * R_DIM + lrow) * D_DIM + cseg * 16;
    const uint32_t stB = (uint32_t)(lrow * SR_ROWB + cseg * 32);

    // A loader: threads < 128, gathered enc rows (64 x 32 per chunk)
    const bool aload = tid < 128;
    int tok = 0;
    if (aload) {
        int m = m0 + (tid >> 1);
        tok = (m < cnt) ? (g_rows[e * CAP + m] >> 1) : 0;
    }
    const float* aG = g_enc + (size_t)tok * D_DIM + cseg * 16;
    const uint32_t stA = (uint32_t)((tid >> 1) * SR_ROWB + cseg * 32);

    const uint32_t aFrag = (uint32_t)((wm * 32 + (lane & 15)) * SR_ROWB) + (uint32_t)((lane >> 4) * 16);
    const uint32_t bFrag = (uint32_t)((wn * 32 + (lane & 7)) * SR_ROWB) + (uint32_t)((lane >> 3) * 16);

    float acc[2][4][4];
#pragma unroll
    for (int i = 0; i < 2; i++)
#pragma unroll
        for (int j = 0; j < 4; j++)
#pragma unroll
            for (int q = 0; q < 4; q++) acc[i][j][q] = 0.0f;

    float4 ra[4], rb[4];
    const int NC = D_DIM / 32;

    // prologue
#pragma unroll
    for (int j = 0; j < 4; j++) rb[j] = *(const float4*)(bG + j * 4);
    if (aload)
#pragma unroll
        for (int j = 0; j < 4; j++) ra[j] = *(const float4*)(aG + j * 4);
    {
        const uint32_t stg = sb;
        uint32_t h[8], l[8];
#pragma unroll
        for (int j = 0; j < 4; j++) {
            split2(rb[j].x, rb[j].y, h[2 * j], l[2 * j]);
            split2(rb[j].z, rb[j].w, h[2 * j + 1], l[2 * j + 1]);
        }
        sts_v4u(stg + E1_BHI + stB,      h[0], h[1], h[2], h[3]);
        sts_v4u(stg + E1_BHI + stB + 16, h[4], h[5], h[6], h[7]);
        sts_v4u(stg + E1_BLO + stB,      l[0], l[1], l[2], l[3]);
        sts_v4u(stg + E1_BLO + stB + 16, l[4], l[5], l[6], l[7]);
        if (aload) {
#pragma unroll
            for (int j = 0; j < 4; j++) {
                split2(ra[j].x, ra[j].y, h[2 * j], l[2 * j]);
                split2(ra[j].z, ra[j].w, h[2 * j + 1], l[2 * j + 1]);
            }
            sts_v4u(stg + E1_AHI + stA,      h[0], h[1], h[2], h[3]);
            sts_v4u(stg + E1_AHI + stA + 16, h[4], h[5], h[6], h[7]);
            sts_v4u(stg + E1_ALO + stA,      l[0], l[1], l[2], l[3]);
            sts_v4u(stg + E1_ALO + stA + 16, l[4], l[5], l[6], l[7]);
        }
    }
    __syncthreads();

#pragma unroll 1
    for (int c = 0; c < NC; c++) {
        if (c + 1 < NC) {
            const int koff = (c + 1) * 32;
#pragma unroll
            for (int j = 0; j < 4; j++) rb[j] = *(const float4*)(bG + koff + j * 4);
            if (aload)
#pragma unroll
                for (int j = 0; j < 4; j++) ra[j] = *(const float4*)(aG + koff + j * 4);
        }
        const uint32_t stg = sb + (uint32_t)(c & 1) * E1_STAGE;
        uint32_t AH[2][2][4], AL[2][2][4];
#pragma unroll
        for (int mi = 0; mi < 2; mi++)
#pragma unroll
            for (int kf = 0; kf < 2; kf++) {
                const uint32_t off = aFrag + (uint32_t)(mi * 16 * SR_ROWB) + (uint32_t)(kf * 32);
                ldsm4(AH[mi][kf], stg + E1_AHI + off);
                ldsm4(AL[mi][kf], stg + E1_ALO + off);
            }
#pragma unroll
        for (int ni = 0; ni < 4; ni++) {
            uint32_t BH[4], BL[4];
            const uint32_t boff = bFrag + (uint32_t)(ni * 8 * SR_ROWB);
            ldsm4(BH, stg + E1_BHI + boff);
            ldsm4(BL, stg + E1_BLO + boff);
#pragma unroll
            for (int mi = 0; mi < 2; mi++) {
                mma_f16(acc[mi][ni], AH[mi][0], BH[0], BH[1]);
                mma_f16(acc[mi][ni], AH[mi][1], BH[2], BH[3]);
                mma_f16(acc[mi][ni], AH[mi][0], BL[0], BL[1]);
                mma_f16(acc[mi][ni], AH[mi][1], BL[2], BL[3]);
                mma_f16(acc[mi][ni], AL[mi][0], BH[0], BH[1]);
                mma_f16(acc[mi][ni], AL[mi][1], BH[2], BH[3]);
            }
        }
        if (c + 1 < NC) {
            const uint32_t stg2 = sb + (uint32_t)((c + 1) & 1) * E1_STAGE;
            uint32_t h[8], l[8];
#pragma unroll
            for (int j = 0; j < 4; j++) {
                split2(rb[j].x, rb[j].y, h[2 * j], l[2 * j]);
                split2(rb[j].z, rb[j].w, h[2 * j + 1], l[2 * j + 1]);
            }
            sts_v4u(stg2 + E1_BHI + stB,      h[0], h[1], h[2], h[3]);
            sts_v4u(stg2 + E1_BHI + stB + 16, h[4], h[5], h[6], h[7]);
            sts_v4u(stg2 + E1_BLO + stB,      l[0], l[1], l[2], l[3]);
            sts_v4u(stg2 + E1_BLO + stB + 16, l[4], l[5], l[6], l[7]);
            if (aload) {
#pragma unroll
                for (int j = 0; j < 4; j++) {
                    split2(ra[j].x, ra[j].y, h[2 * j], l[2 * j]);
                    split2(ra[j].z, ra[j].w, h[2 * j + 1], l[2 * j + 1]);
                }
                sts_v4u(stg2 + E1_AHI + stA,      h[0], h[1], h[2], h[3]);
                sts_v4u(stg2 + E1_AHI + stA + 16, h[4], h[5], h[6], h[7]);
                sts_v4u(stg2 + E1_ALO + stA,      l[0], l[1], l[2], l[3]);
                sts_v4u(stg2 + E1_ALO + stA + 16, l[4], l[5], l[6], l[7]);
            }
            __syncthreads();
        }
    }

    const int g = lane >> 2;
    const int t = lane & 3;
#pragma unroll
    for (int mi = 0; mi < 2; mi++) {
        const int r0 = m0 + wm * 32 + mi * 16 + g;
        const int r1 = r0 + 8;
#pragma unroll
        for (int ni = 0; ni < 4; ni++) {
            const int col = wn * 32 + ni * 8 + 2 * t;
            if (r0 < cnt) {
                float2 o;
                o.x = silu_f(acc[mi][ni][0]);
                o.y = silu_f(acc[mi][ni][1]);
                *(float2*)(g_h + ((size_t)e * CAP + r0) * R_DIM + col) = o;
            }
            if (r1 < cnt) {
                float2 o;
                o.x = silu_f(acc[mi][ni][2]);
                o.y = silu_f(acc[mi][ni][3]);
                *(float2*)(g_h + ((size_t)e * CAP + r1) * R_DIM + col) = o;
            }
        }
    }
}

// =====================================================================
// Stage 6: dbuf[n] = (w * gamma_e) * (H @ V_e^T) via fp16-split mma
// BM=64, BN=128, BK=32, NC=4; 8 warps: 2(m32) x 4(n32)
// =====================================================================
__global__ void __launch_bounds__(256, 1) k_exp2_mma(const float* __restrict__ V,
                                                     const float* __restrict__ gamma) {
    const int e = blockIdx.z;
    const int cnt = g_cnt[e];
    const int m0 = blockIdx.y * 64;
    if (m0 >= cnt) return;
    const int n0 = blockIdx.x * 128;
    extern __shared__ char smraw[];
    const uint32_t sb = smem_u32(smraw);
    const int tid = threadIdx.x;
    const int lane = tid & 31;
    const int wid = tid >> 5;
    const int wm = wid & 1;
    const int wn = wid >> 1;

    const int lrow = tid >> 1;
    const int cseg = tid & 1;
    // B: rows of V[e] (d = n0 + lrow), k = r
    const float* bG = V + ((size_t)e * D_DIM + n0 + lrow) * R_DIM + cseg * 16;
    const uint32_t stB = (uint32_t)(lrow * SR_ROWB + cseg * 32);
    // A: contiguous g_h rows
    const bool aload = tid < 128;
    const float* aG = g_h + ((size_t)e * CAP + m0 + (tid >> 1)) * R_DIM + cseg * 16;
    const uint32_t stA = (uint32_t)((tid >> 1) * SR_ROWB + cseg * 32);

    const uint32_t aFrag = (uint32_t)((wm * 32 + (lane & 15)) * SR_ROWB) + (uint32_t)((lane >> 4) * 16);
    const uint32_t bFrag = (uint32_t)((wn * 32 + (lane & 7)) * SR_ROWB) + (uint32_t)((lane >> 3) * 16);

    float acc[2][4][4];
#pragma unroll
    for (int i = 0; i < 2; i++)
#pragma unroll
        for (int j = 0; j < 4; j++)
#pragma unroll
            for (int q = 0; q < 4; q++) acc[i][j][q] = 0.0f;

    float4 ra[4], rb[4];
    const int NC = R_DIM / 32;           // 4

#pragma unroll
    for (int j = 0; j < 4; j++) rb[j] = *(const float4*)(bG + j * 4);
    if (aload)
#pragma unroll
        for (int j = 0; j < 4; j++) ra[j] = *(const float4*)(aG + j * 4);
    {
        const uint32_t stg = sb;
        uint32_t h[8], l[8];
#pragma unroll
        for (int j = 0; j < 4; j++) {
            split2(rb[j].x, rb[j].y, h[2 * j], l[2 * j]);
            split2(rb[j].z, rb[j].w, h[2 * j + 1], l[2 * j + 1]);
        }
        sts_v4u(stg + E1_BHI + stB,      h[0], h[1], h[2], h[3]);
        sts_v4u(stg + E1_BHI + stB + 16, h[4], h[5], h[6], h[7]);
        sts_v4u(stg + E1_BLO + stB,      l[0], l[1], l[2], l[3]);
        sts_v4u(stg + E1_BLO + stB + 16, l[4], l[5], l[6], l[7]);
        if (aload) {
#pragma unroll
            for (int j = 0; j < 4; j++) {
                split2(ra[j].x, ra[j].y, h[2 * j], l[2 * j]);
                split2(ra[j].z, ra[j].w, h[2 * j + 1], l[2 * j + 1]);
            }
            sts_v4u(stg + E1_AHI + stA,      h[0], h[1], h[2], h[3]);
            sts_v4u(stg + E1_AHI + stA + 16, h[4], h[5], h[6], h[7]);
            sts_v4u(stg + E1_ALO + stA,      l[0], l[1], l[2], l[3]);
            sts_v4u(stg + E1_ALO + stA + 16, l[4], l[5], l[6], l[7]);
        }
    }
    __syncthreads();

#pragma unroll 1
    for (int c = 0; c < NC; c++) {
        if (c + 1 < NC) {
            const int koff = (c + 1) * 32;
#pragma unroll
            for (int j = 0; j < 4; j++) rb[j] = *(const float4*)(bG + koff + j * 4);
            if (aload)
#pragma unroll
                for (int j = 0; j < 4; j++) ra[j] = *(const float4*)(aG + koff + j * 4);
        }
        const uint32_t stg = sb + (uint32_t)(c & 1) * E1_STAGE;
        uint32_t AH[2][2][4], AL[2][2][4];
#pragma unroll
        for (int mi = 0; mi < 2; mi++)
#pragma unroll
            for (int kf = 0; kf < 2; kf++) {
                const uint32_t off = aFrag + (uint32_t)(mi * 16 * SR_ROWB) + (uint32_t)(kf * 32);
                ldsm4(AH[mi][kf], stg + E1_AHI + off);
                ldsm4(AL[mi][kf], stg + E1_ALO + off);
            }
#pragma unroll
        for (int ni = 0; ni < 4; ni++) {
            uint32_t BH[4], BL[4];
            const uint32_t boff = bFrag + (uint32_t)(ni * 8 * SR_ROWB);
            ldsm4(BH, stg + E1_BHI + boff);
            ldsm4(BL, stg + E1_BLO + boff);
#pragma unroll
            for (int mi = 0; mi < 2; mi++) {
                mma_f16(acc[mi][ni], AH[mi][0], BH[0], BH[1]);
                mma_f16(acc[mi][ni], AH[mi][1], BH[2], BH[3]);
                mma_f16(acc[mi][ni], AH[mi][0], BL[0], BL[1]);
                mma_f16(acc[mi][ni], AH[mi][1], BL[2], BL[3]);
                mma_f16(acc[mi][ni], AL[mi][0], BH[0], BH[1]);
                mma_f16(acc[mi][ni], AL[mi][1], BH[2], BH[3]);
            }
        }
        if (c + 1 < NC) {
            const uint32_t stg2 = sb + (uint32_t)((c + 1) & 1) * E1_STAGE;
            uint32_t h[8], l[8];
#pragma unroll
            for (int j = 0; j < 4; j++) {
                split2(rb[j].x, rb[j].y, h[2 * j], l[2 * j]);
                split2(rb[j].z, rb[j].w, h[2 * j + 1], l[2 * j + 1]);
            }
            sts_v4u(stg2 + E1_BHI + stB,      h[0], h[1], h[2], h[3]);
            sts_v4u(stg2 + E1_BHI + stB + 16, h[4], h[5], h[6], h[7]);
            sts_v4u(stg2 + E1_BLO + stB,      l[0], l[1], l[2], l[3]);
            sts_v4u(stg2 + E1_BLO + stB + 16, l[4], l[5], l[6], l[7]);
            if (aload) {
#pragma unroll
                for (int j = 0; j < 4; j++) {
                    split2(ra[j].x, ra[j].y, h[2 * j], l[2 * j]);
                    split2(ra[j].z, ra[j].w, h[2 * j + 1], l[2 * j + 1]);
                }
                sts_v4u(stg2 + E1_AHI + stA,      h[0], h[1], h[2], h[3]);
                sts_v4u(stg2 + E1_AHI + stA + 16, h[4], h[5], h[6], h[7]);
                sts_v4u(stg2 + E1_ALO + stA,      l[0], l[1], l[2], l[3]);
                sts_v4u(stg2 + E1_ALO + stA + 16, l[4], l[5], l[6], l[7]);
            }
            __syncthreads();
        }
    }

    const float gm = gamma[e];
    const int g = lane >> 2;
    const int t = lane & 3;
#pragma unroll
    for (int mi = 0; mi < 2; mi++) {
        const int r0 = m0 + wm * 32 + mi * 16 + g;
        const int r1 = r0 + 8;
        int n_0 = -1, n_1 = -1;
        float s0 = 0.f, s1 = 0.f;
        if (r0 < cnt) { n_0 = g_rows[e * CAP + r0]; s0 = g_w[n_0] * gm; }
        if (r1 < cnt) { n_1 = g_rows[e * CAP + r1]; s1 = g_w[n_1] * gm; }
#pragma unroll
        for (int ni = 0; ni < 4; ni++) {
            const int col = n0 + wn * 32 + ni * 8 + 2 * t;
            if (n_0 >= 0) {
                float2 o;
                o.x = acc[mi][ni][0] * s0;
                o.y = acc[mi][ni][1] * s0;
                *(float2*)(g_dbuf + (size_t)n_0 * D_DIM + col) = o;
            }
            if (n_1 >= 0) {
                float2 o;
                o.x = acc[mi][ni][2] * s1;
                o.y = acc[mi][ni][3] * s1;
                *(float2*)(g_dbuf + (size_t)n_1 * D_DIM + col) = o;
            }
        }
    }
}

// =====================================================================
// Stage 7: combine
// =====================================================================
__global__ void __launch_bounds__(512) k_combine(float* __restrict__ y) {
    const int t = blockIdx.x;
    const int d4 = threadIdx.x;
    const float4* enc4 = (const float4*)g_enc;
    const float4* db4 = (const float4*)g_dbuf;
    float4 r = enc4[(size_t)t * 512 + d4];
    const float w0 = g_w[2 * t];
    const float w1 = g_w[2 * t + 1];
    if (w0 > 0.0f) {
        float4 a = db4[(size_t)(2 * t) * 512 + d4];
        r.x += a.x; r.y += a.y; r.z += a.z; r.w += a.w;
    }
    if (w1 > 0.0f) {
        float4 a = db4[(size_t)(2 * t + 1) * 512 + d4];
        r.x += a.x; r.y += a.y; r.z += a.z; r.w += a.w;
    }
    ((float4*)y)[(size_t)t * 512 + d4] = r;
}

// =====================================================================
extern "C" void kernel_launch(void* const* d_in, const int* in_sizes, int n_in,
                              void* d_out, int out_size) {
    const float* x     = (const float*)d_in[0];
    const float* We    = (const float*)d_in[1];
    const float* be    = (const float*)d_in[2];
    const float* Wg    = (const float*)d_in[3];
    const float* U     = (const float*)d_in[4];
    const float* V     = (const float*)d_in[5];
    const float* gamma = (const float*)d_in[6];
    float* y = (float*)d_out;

    cudaFuncSetAttribute(k_enc_mma, cudaFuncAttributeMaxDynamicSharedMemorySize, ENC_SMEM);
    cudaFuncSetAttribute(k_exp1_mma, cudaFuncAttributeMaxDynamicSharedMemorySize, E1_SMEM);
    cudaFuncSetAttribute(k_exp2_mma, cudaFuncAttributeMaxDynamicSharedMemorySize, E1_SMEM);

    dim3 gEnc(D_DIM / 128, B_TOK / 128);            // 16 x 128
    k_enc_mma<<<gEnc, 256, ENC_SMEM>>>(x, We, be);

    dim3 gLog(1, B_TOK / 128);                      // 1 x 128
    k_gemm_logits<<<gLog, 256>>>(Wg);

    k_route<<<B_TOK / 256, 256>>>();

    k_capacity<<<E_NUM, 256>>>();

    dim3 gE1(CAP / 64, E_NUM);                      // 10 x 64
    k_exp1_mma<<<gE1, 256, E1_SMEM>>>(U);

    dim3 gE2(D_DIM / 128, CAP / 64, E_NUM);         // 16 x 10 x 64
    k_exp2_mma<<<gE2, 256, E1_SMEM>>>(V, gamma);

    k_combine<<<B_TOK, 512>>>(y);
}